// round 3
// baseline (speedup 1.0000x reference)
#include <cuda_runtime.h>
#include <stdint.h>

#define NALGOS 64
#define NTASKS 1024
#define LXN    512
#define FULLMASK 0xffffffffu

// Scratch (no allocations allowed).
// g_G layout (permuted for phase1): g_G[s*512 + lane*16 + i] = TM[lx[s]][lx[32*i+lane]]
__device__ float g_G[LXN * LXN];
__device__ float g_u[NALGOS * LXN];

// 2*sigmoid(z) - 1 == tanh(z/2): single MUFU.TANH (lat 16), abs err ~2^-11.
__device__ __forceinline__ float tanh_fast(float x) {
    float y;
    asm("tanh.approx.f32 %0, %1;" : "=f"(y) : "f"(x));
    return y;
}

// ---------------------------------------------------------------------------
// Kernel 0: gather G in phase1's permuted layout.
// ---------------------------------------------------------------------------
__global__ void build_G(const int* __restrict__ lx, const float* __restrict__ TM) {
    int s = blockIdx.x;
    int t = threadIdx.x;                     // global column index 0..511
    int row = __ldg(lx + s);
    int col = __ldg(lx + t);
    g_G[s * LXN + (t & 31) * 16 + (t >> 5)] = __ldg(TM + row * NTASKS + col);
}

// ---------------------------------------------------------------------------
// Phase 1: serial chain, one warp per algo. Lane l tracks the 16 columns
// lx[32*i + l]. Active chunk c covers steps/cols [32c,32c+32): owner of step s
// is lane s%32, register slot i = s/32 = c. A shadow scalar `ract` tracks the
// lane's active-chunk column so the hot loop needs no dynamic register index;
// it is re-seeded from r[c] by 16 static SELs at each chunk boundary.
// Hot loop body ~3KB -> resident in L0 I$ (the round-2 kernel's 450KB
// fully-unrolled body thrashed instruction fetch on a single warp).
// ---------------------------------------------------------------------------
__global__ void __launch_bounds__(32, 1) phase1(
    const int* __restrict__ lx, const float* __restrict__ diff,
    const float* __restrict__ eff_, const float* __restrict__ mem_,
    const float* __restrict__ boost_) {
    int a = blockIdx.x;
    int lane = threadIdx.x;
    float mem = __ldg(mem_ + a), eff = __ldg(eff_ + a), boost = __ldg(boost_ + a);

    float r[16], c2[16];
#pragma unroll
    for (int i = 0; i < 16; ++i) {
        r[i] = 0.0f;
        c2[i] = 0.5f / __ldg(diff + __ldg(lx + 32 * i + lane));
    }

    // depth-4 register pipelines: gb = full row (16 floats as 4x float4),
    // ga = active-chunk scalar for the shadow accumulator.
    float4 gb[4][4];
    float  ga[4];
#pragma unroll
    for (int q = 0; q < 4; ++q) {
        const float4* gp = (const float4*)(g_G + q * LXN + lane * 16);
#pragma unroll
        for (int x = 0; x < 4; ++x) gb[q][x] = __ldg(gp + x);
        ga[q] = __ldg(g_G + q * LXN + lane * 16 + 0);   // chunk 0
    }

    float u_val = eff;                   // p[0]=0 -> u[0]=eff (all lanes hold it)
    float* uout = g_u + a * LXN;

#pragma unroll 1
    for (int c = 0; c < 16; ++c) {
        // seed shadow regs for this chunk (static-index SELs, no spill)
        float ract = 0.0f, c2act = 0.0f;
#pragma unroll
        for (int i = 0; i < 16; ++i)
            if (i == c) { ract = r[i]; c2act = c2[i]; }
        // chunk-boundary handoff: u for step 32c produced by lane 0
        if (c > 0 && lane == 0)
            u_val = fmaf(tanh_fast(ract * c2act), boost, eff);

#pragma unroll 4
        for (int k = 0; k < 32; ++k) {
            int s = c * 32 + k;
            float u = __shfl_sync(FULLMASK, u_val, k);
            if (lane == 0) uout[s] = u;
            int q = k & 3;                        // static under unroll-4
#pragma unroll
            for (int x = 0; x < 4; ++x) {
                float4 g = gb[q][x];
                r[4 * x + 0] = fmaf(r[4 * x + 0], mem, g.x * u);
                r[4 * x + 1] = fmaf(r[4 * x + 1], mem, g.y * u);
                r[4 * x + 2] = fmaf(r[4 * x + 2], mem, g.z * u);
                r[4 * x + 3] = fmaf(r[4 * x + 3], mem, g.w * u);
            }
            ract = fmaf(ract, mem, ga[q] * u);    // shadow of r[c]
            // refill pipeline slot with step s+4
            if (s + 4 < LXN) {
                const float4* gp = (const float4*)(g_G + (s + 4) * LXN + lane * 16);
#pragma unroll
                for (int x = 0; x < 4; ++x) gb[q][x] = __ldg(gp + x);
                int cn = (k + 4 < 32) ? c : c + 1;
                ga[q] = __ldg(g_G + (s + 4) * LXN + lane * 16 + cn);
            }
            // produce u[s+1] on its owner lane (k=31 case handled at boundary)
            if (k < 31 && lane == k + 1)
                u_val = fmaf(tanh_fast(ract * c2act), boost, eff);
        }
    }
}

// ---------------------------------------------------------------------------
// Phase 2: 65536 independent column scans. 32x32 smem transpose per warp so
// all STG to out[a][j][t] (t innermost, stride 513) are coalesced.
// ---------------------------------------------------------------------------
__global__ void __launch_bounds__(128) phase2(
    const int* __restrict__ lx, const float* __restrict__ TM,
    const float* __restrict__ diff, const float* __restrict__ mem_,
    float* __restrict__ out) {
    int a   = blockIdx.y;
    int tid = threadIdx.x;
    int j   = blockIdx.x * 128 + tid;

    __shared__ float u_sh[LXN];
    __shared__ int   off_sh[LXN];
    __shared__ float tbuf[4][32][33];   // [warp][j-row][t] ; +1 pad: conflict-free

    for (int i = tid; i < LXN; i += 128) {
        u_sh[i]   = g_u[a * LXN + i];
        off_sh[i] = __ldg(lx + i) << 10;   // lx[s] * NTASKS
    }
    __syncthreads();

    float mem = __ldg(mem_ + a);
    float c2  = 0.5f / __ldg(diff + j);
    float r   = 0.0f;
    int warp = tid >> 5, lane = tid & 31;

    unsigned obase = (unsigned)(a * NTASKS + j) * 513u;
    out[obase] = 0.0f;                                  // step-0 zeros
    unsigned tbase = (unsigned)(a * NTASKS + blockIdx.x * 128 + warp * 32) * 513u
                     + 1u + (unsigned)lane;

    for (int c = 0; c < 16; ++c) {
#pragma unroll 8
        for (int k = 0; k < 32; ++k) {
            int s = c * 32 + k;
            float val = __ldg(TM + off_sh[s] + j);      // coalesced, L2-hot
            r = fmaf(r, mem, val * u_sh[s]);
            tbuf[warp][lane][k] = tanh_fast(r * c2);
        }
        __syncwarp();
        unsigned ob = tbase + (unsigned)(c * 32);
#pragma unroll 8
        for (int row = 0; row < 32; ++row)
            out[ob + (unsigned)row * 513u] = tbuf[warp][row][lane];
        __syncwarp();
    }
}

// ---------------------------------------------------------------------------
extern "C" void kernel_launch(void* const* d_in, const int* in_sizes, int n_in,
                              void* d_out, int out_size) {
    const int*   lx    = (const int*)  d_in[0];
    const float* TM    = (const float*)d_in[1];
    const float* diff  = (const float*)d_in[2];
    const float* eff   = (const float*)d_in[3];
    const float* mem   = (const float*)d_in[4];
    const float* boost = (const float*)d_in[5];
    float* out = (float*)d_out;

    build_G<<<LXN, LXN>>>(lx, TM);
    phase1<<<NALGOS, 32>>>(lx, diff, eff, mem, boost);
    phase2<<<dim3(NTASKS / 128, NALGOS), 128>>>(lx, TM, diff, mem, out);
}

// round 4
// speedup vs baseline: 1.2105x; 1.2105x over previous
#include <cuda_runtime.h>
#include <stdint.h>

#define NALGOS 64
#define NTASKS 1024
#define LXN    512
#define FULLMASK 0xffffffffu

// Scratch (no allocations allowed).
// g_G[s*512 + t] = TM[lx[s]][lx[t]]  (t contiguous -> coalesced lane reads)
__device__ float g_G[LXN * LXN];
__device__ float g_u[NALGOS * LXN];

// 2*sigmoid(z) - 1 == tanh(z/2): single MUFU.TANH, abs err ~2^-11.
__device__ __forceinline__ float tanh_fast(float x) {
    float y;
    asm("tanh.approx.f32 %0, %1;" : "=f"(y) : "f"(x));
    return y;
}

// ---------------------------------------------------------------------------
// Kernel 0: G[s][t] = TM[lx[s]][lx[t]]
// ---------------------------------------------------------------------------
__global__ void build_G(const int* __restrict__ lx, const float* __restrict__ TM) {
    int s = blockIdx.x;
    int t = threadIdx.x;
    int row = __ldg(lx + s);
    int col = __ldg(lx + t);
    g_G[s * LXN + t] = __ldg(TM + row * NTASKS + col);
}

// ---------------------------------------------------------------------------
// Phase 1: chunked linear recurrence, one block (8 warps) per algo.
//   chunk c = steps [32c, 32c+32)
//   Warp 0 ("chain"): serial 32-step recursion on the chunk's own 32 columns
//     (lane l owns column lx[32c+l]); simultaneously accumulates racc2 =
//     this chunk's contribution to NEXT chunk's 32 columns.
//   Warps 1-7 ("bulk"): one chunk behind, maintain full 512-col state R
//     (cols (w-1)*32 + l + 224*i). Owner warp of chunk c+1 publishes boundary
//     values (double-buffered smem) so the chain can continue seamlessly:
//       racc_next = Bnext * mem^32 + racc2.
// Critical path ~ 16 * (32 * ~62cyc + barrier) ~ 34K cycles.
// ---------------------------------------------------------------------------
__global__ void __launch_bounds__(256, 1) phase1(
    const int* __restrict__ lx, const float* __restrict__ diff,
    const float* __restrict__ eff_, const float* __restrict__ mem_,
    const float* __restrict__ boost_) {
    int a   = blockIdx.x;
    int tid = threadIdx.x;
    int w   = tid >> 5, l = tid & 31;

    __shared__ float u_sh[LXN];
    __shared__ float c2_sh[LXN];
    __shared__ float Bnext_sh[2][32];

    float mem = __ldg(mem_ + a), eff = __ldg(eff_ + a), boost = __ldg(boost_ + a);
    float m2 = mem * mem, m4 = m2 * m2, m8 = m4 * m4, m16 = m8 * m8;
    float M32 = m16 * m16;

    for (int t = tid; t < LXN; t += 256)
        c2_sh[t] = 0.5f / __ldg(diff + __ldg(lx + t));
    __syncthreads();

    if (w == 0) {
        // ---------------- chain warp ----------------
        float racc = 0.0f, racc2 = 0.0f;
        float c2l = c2_sh[l];
        float u_val = eff;                       // lane0 k=0: tanh(0)=0 -> eff

#pragma unroll 1
        for (int c = 0; c < 16; ++c) {
            int t0 = c * 32;
            const float* gArow = g_G + t0 + l;         // + s*512
            const float* gBrow = g_G + t0 + 32 + l;
            bool hasB = (c < 15);

            // depth-8 register pipeline over steps
            float gA[8], gB[8];
#pragma unroll
            for (int q = 0; q < 8; ++q) {
                gA[q] = __ldg(gArow + (t0 + q) * LXN);
                gB[q] = hasB ? __ldg(gBrow + (t0 + q) * LXN) : 0.0f;
            }
#pragma unroll 8
            for (int k = 0; k < 32; ++k) {
                int q = k & 7;
                if (l == k)
                    u_val = fmaf(tanh_fast(racc * c2l), boost, eff);
                float u = __shfl_sync(FULLMASK, u_val, k);
                if (l == k) u_sh[t0 + k] = u;
                racc  = fmaf(racc,  mem, gA[q] * u);
                racc2 = fmaf(racc2, mem, gB[q] * u);
                if (k + 8 < 32) {
                    gA[q] = __ldg(gArow + (t0 + k + 8) * LXN);
                    gB[q] = hasB ? __ldg(gBrow + (t0 + k + 8) * LXN) : 0.0f;
                }
            }
            __syncthreads();                      // joint with bulk warps
            if (c < 15) {
                racc  = fmaf(Bnext_sh[(c + 1) & 1][l], M32, racc2);
                racc2 = 0.0f;
                c2l   = c2_sh[t0 + 32 + l];
            }
        }
        // final u_sh -> g_u copy (chain warp, coalesced)
        __syncthreads();
        for (int t = l; t < LXN; t += 32)
            g_u[a * LXN + t] = u_sh[t];
    } else {
        // ---------------- bulk warps 1..7 ----------------
        int base0 = (w - 1) * 32 + l;            // cols: base0 + 224*i
        bool has3 = (base0 + 448 < LXN);         // warps 1,2 carry a 3rd col
        float R0 = 0.0f, R1 = 0.0f, R2v = 0.0f;

#pragma unroll 1
        for (int c = 0; c < 16; ++c) {
            if (c >= 1) {
                int s0 = (c - 1) * 32;
                const float* g0 = g_G + base0;
#pragma unroll 4
                for (int k = 0; k < 32; ++k) {
                    float u = u_sh[s0 + k];      // LDS broadcast
                    const float* gr = g0 + (s0 + k) * LXN;
                    R0 = fmaf(R0, mem, __ldg(gr) * u);
                    R1 = fmaf(R1, mem, __ldg(gr + 224) * u);
                    if (has3) R2v = fmaf(R2v, mem, __ldg(gr + 448) * u);
                }
            }
            // publish boundary for chunk b = c+1 (owner: warp (b%7)+1, slot b/7)
            int b = c + 1;
            if (b <= 15 && (w - 1) == (b % 7)) {
                int i = b / 7;
                float Rv = (i == 0) ? R0 : (i == 1) ? R1 : R2v;
                Bnext_sh[b & 1][l] = Rv;
            }
            __syncthreads();
        }
        __syncthreads();   // match chain's final barrier
    }
}

// ---------------------------------------------------------------------------
// Phase 2: 65536 independent column scans (UNCHANGED from round 2/3 for clean
// attribution). 32x32 smem transpose per warp -> coalesced STG.
// ---------------------------------------------------------------------------
__global__ void __launch_bounds__(128) phase2(
    const int* __restrict__ lx, const float* __restrict__ TM,
    const float* __restrict__ diff, const float* __restrict__ mem_,
    float* __restrict__ out) {
    int a   = blockIdx.y;
    int tid = threadIdx.x;
    int j   = blockIdx.x * 128 + tid;

    __shared__ float u_sh[LXN];
    __shared__ int   off_sh[LXN];
    __shared__ float tbuf[4][32][33];

    for (int i = tid; i < LXN; i += 128) {
        u_sh[i]   = g_u[a * LXN + i];
        off_sh[i] = __ldg(lx + i) << 10;
    }
    __syncthreads();

    float mem = __ldg(mem_ + a);
    float c2  = 0.5f / __ldg(diff + j);
    float r   = 0.0f;
    int warp = tid >> 5, lane = tid & 31;

    unsigned obase = (unsigned)(a * NTASKS + j) * 513u;
    out[obase] = 0.0f;
    unsigned tbase = (unsigned)(a * NTASKS + blockIdx.x * 128 + warp * 32) * 513u
                     + 1u + (unsigned)lane;

    for (int c = 0; c < 16; ++c) {
#pragma unroll 8
        for (int k = 0; k < 32; ++k) {
            int s = c * 32 + k;
            float val = __ldg(TM + off_sh[s] + j);
            r = fmaf(r, mem, val * u_sh[s]);
            tbuf[warp][lane][k] = tanh_fast(r * c2);
        }
        __syncwarp();
        unsigned ob = tbase + (unsigned)(c * 32);
#pragma unroll 8
        for (int row = 0; row < 32; ++row)
            out[ob + (unsigned)row * 513u] = tbuf[warp][row][lane];
        __syncwarp();
    }
}

// ---------------------------------------------------------------------------
extern "C" void kernel_launch(void* const* d_in, const int* in_sizes, int n_in,
                              void* d_out, int out_size) {
    const int*   lx    = (const int*)  d_in[0];
    const float* TM    = (const float*)d_in[1];
    const float* diff  = (const float*)d_in[2];
    const float* eff   = (const float*)d_in[3];
    const float* mem   = (const float*)d_in[4];
    const float* boost = (const float*)d_in[5];
    float* out = (float*)d_out;

    build_G<<<LXN, LXN>>>(lx, TM);
    phase1<<<NALGOS, 256>>>(lx, diff, eff, mem, boost);
    phase2<<<dim3(NTASKS / 128, NALGOS), 128>>>(lx, TM, diff, mem, out);
}